// round 1
// baseline (speedup 1.0000x reference)
#include <cuda_runtime.h>

#define T_STEPS 512
#define BATCH   64
#define IDIM    256
#define HDIM    512
#define NCTA    128
#define NTHR    128
#define JCOL    4            // h-columns per CTA
#define GR      16           // gate rows per CTA (4 gates * JCOL)
#define CK      64           // K staging chunk
#define CKP     68           // padded chunk row stride (floats)
#define WXS     258          // Wx row stride (floats, padded)
#define WHS     514          // Wh row stride (floats, padded)
#define GSTR    66           // gate-exchange row stride

typedef unsigned long long ull;

// persistent state (static device arrays: no allocation in kernel_launch)
__device__ float g_hbuf[2][BATCH * HDIM];
__device__ unsigned int g_bar_count;
__device__ unsigned int g_bar_epoch;

__device__ __forceinline__ ull fma2(ull a, ull b, ull c) {
    ull d;
    asm("fma.rn.f32x2 %0, %1, %2, %3;" : "=l"(d) : "l"(a), "l"(b), "l"(c));
    return d;
}

__device__ __forceinline__ float hsum2(ull a) {
    return __uint_as_float((unsigned)(a & 0xffffffffu)) +
           __uint_as_float((unsigned)(a >> 32));
}

__device__ __forceinline__ float sigmoidf_(float v) {
    return 1.0f / (1.0f + expf(-v));
}

// total shared floats
#define SMEM_FLOATS (GR*WXS + GR*WHS + BATCH*CKP + GR*GSTR + JCOL*BATCH + GR + 4)

__global__ void __launch_bounds__(NTHR, 1)
lstm_persistent(const float* __restrict__ x,
                const float* __restrict__ Wf, const float* __restrict__ bWf,
                const float* __restrict__ Wi, const float* __restrict__ bWi,
                const float* __restrict__ Wo, const float* __restrict__ bWo,
                const float* __restrict__ Wc, const float* __restrict__ bWc,
                const float* __restrict__ Uf, const float* __restrict__ bUf,
                const float* __restrict__ Ui, const float* __restrict__ bUi,
                const float* __restrict__ Uo, const float* __restrict__ bUo,
                const float* __restrict__ Uc, const float* __restrict__ bUc,
                float* __restrict__ out)
{
    extern __shared__ float sm[];
    float* Wx  = sm;                          // GR * WXS
    float* Wh  = Wx + GR * WXS;               // GR * WHS
    float* ash = Wh + GR * WHS;               // BATCH * CKP (16B aligned)
    float* gsm = ash + BATCH * CKP;           // GR * GSTR
    float* csm = gsm + GR * GSTR;             // JCOL * BATCH
    float* bsm = csm + JCOL * BATCH;          // GR
    unsigned* ebase = (unsigned*)(bsm + GR);

    const int tid = threadIdx.x;
    const int cg  = tid & 7;                  // handles gate rows cg and cg+8
    const int bg  = tid >> 3;                 // handles batch rows 4*bg..4*bg+3
    const int j0  = blockIdx.x * JCOL;

    // ---- prologue: weights + bias into SMEM, c state = 0 ----
    {
        const float* Wg[4]  = {Wf, Wi, Wo, Wc};
        const float* Ug[4]  = {Uf, Ui, Uo, Uc};
        const float* bWg[4] = {bWf, bWi, bWo, bWc};
        const float* bUg[4] = {bUf, bUi, bUo, bUc};

        for (int idx = tid; idx < GR * IDIM; idx += NTHR) {
            int row = idx >> 8, k = idx & (IDIM - 1);
            int gate = row >> 2, j = row & 3;
            Wx[row * WXS + k] = Wg[gate][(j0 + j) * IDIM + k];
        }
        for (int idx = tid; idx < GR * HDIM; idx += NTHR) {
            int row = idx >> 9, k = idx & (HDIM - 1);
            int gate = row >> 2, j = row & 3;
            Wh[row * WHS + k] = Ug[gate][(j0 + j) * HDIM + k];
        }
        if (tid < GR) {
            int gate = tid >> 2, j = tid & 3;
            bsm[tid] = bWg[gate][j0 + j] + bUg[gate][j0 + j];
        }
        for (int idx = tid; idx < JCOL * BATCH; idx += NTHR) csm[idx] = 0.0f;
        if (tid == 0) *ebase = *(volatile unsigned*)&g_bar_epoch;
    }
    __syncthreads();
    const unsigned base_epoch = *ebase;

    float* hseq = out;
    float* hfin = out + (size_t)T_STEPS * BATCH * HDIM;
    float* cfin = hfin + BATCH * HDIM;

    const float* wx0 = Wx + cg * WXS;
    const float* wx1 = Wx + (cg + 8) * WXS;
    const float* wh0 = Wh + cg * WHS;
    const float* wh1 = Wh + (cg + 8) * WHS;
    const float* a0p = ash + (bg * 4 + 0) * CKP;
    const float* a1p = ash + (bg * 4 + 1) * CKP;
    const float* a2p = ash + (bg * 4 + 2) * CKP;
    const float* a3p = ash + (bg * 4 + 3) * CKP;

    for (int t = 0; t < T_STEPS; ++t) {
        ull acc00 = 0ull, acc01 = 0ull, acc02 = 0ull, acc03 = 0ull;
        ull acc10 = 0ull, acc11 = 0ull, acc12 = 0ull, acc13 = 0ull;

#define INNER_CHUNK(W0P, W1P)                                          \
        {                                                              \
            const float* w0_ = (W0P);                                  \
            const float* w1_ = (W1P);                                  \
            _Pragma("unroll")                                          \
            for (int kk = 0; kk < CK; kk += 2) {                       \
                ull w0v = *(const ull*)(w0_ + kk);                     \
                ull w1v = *(const ull*)(w1_ + kk);                     \
                ull av;                                                \
                av = *(const ull*)(a0p + kk);                          \
                acc00 = fma2(w0v, av, acc00);                          \
                acc10 = fma2(w1v, av, acc10);                          \
                av = *(const ull*)(a1p + kk);                          \
                acc01 = fma2(w0v, av, acc01);                          \
                acc11 = fma2(w1v, av, acc11);                          \
                av = *(const ull*)(a2p + kk);                          \
                acc02 = fma2(w0v, av, acc02);                          \
                acc12 = fma2(w1v, av, acc12);                          \
                av = *(const ull*)(a3p + kk);                          \
                acc03 = fma2(w0v, av, acc03);                          \
                acc13 = fma2(w1v, av, acc13);                          \
            }                                                          \
        }

        // ---- Phase X: K over IDIM (input projection, fused) ----
        const float* xt = x + (size_t)t * BATCH * IDIM;
        for (int kc = 0; kc < IDIM / CK; ++kc) {
            const float* xbase = xt + kc * CK;
            #pragma unroll
            for (int r = 0; r < (BATCH * CK / 4) / NTHR; ++r) {   // 8
                int idx = tid + r * NTHR;
                int b = idx >> 4;
                int q = idx & 15;
                float4 v = *reinterpret_cast<const float4*>(xbase + b * IDIM + q * 4);
                *reinterpret_cast<float4*>(ash + b * CKP + q * 4) = v;
            }
            __syncthreads();
            INNER_CHUNK(wx0 + kc * CK, wx1 + kc * CK);
            __syncthreads();
        }

        // ---- Phase H: K over HDIM (recurrent part), skipped at t=0 (h0 = 0) ----
        if (t > 0) {
            const float* hprev = g_hbuf[t & 1];
            for (int kc = 0; kc < HDIM / CK; ++kc) {
                const float* hbase = hprev + kc * CK;
                #pragma unroll
                for (int r = 0; r < 8; ++r) {
                    int idx = tid + r * NTHR;
                    int b = idx >> 4;
                    int q = idx & 15;
                    // L2-only load: other SMs wrote this; local L1 may be stale
                    float4 v = __ldcg(reinterpret_cast<const float4*>(hbase + b * HDIM + q * 4));
                    *reinterpret_cast<float4*>(ash + b * CKP + q * 4) = v;
                }
                __syncthreads();
                INNER_CHUNK(wh0 + kc * CK, wh1 + kc * CK);
                __syncthreads();
            }
        }

        // ---- horizontal reduce + bias, exchange gates via SMEM ----
        {
            float b0 = bsm[cg];
            float b1 = bsm[cg + 8];
            gsm[cg * GSTR + bg * 4 + 0]       = hsum2(acc00) + b0;
            gsm[cg * GSTR + bg * 4 + 1]       = hsum2(acc01) + b0;
            gsm[cg * GSTR + bg * 4 + 2]       = hsum2(acc02) + b0;
            gsm[cg * GSTR + bg * 4 + 3]       = hsum2(acc03) + b0;
            gsm[(cg + 8) * GSTR + bg * 4 + 0] = hsum2(acc10) + b1;
            gsm[(cg + 8) * GSTR + bg * 4 + 1] = hsum2(acc11) + b1;
            gsm[(cg + 8) * GSTR + bg * 4 + 2] = hsum2(acc12) + b1;
            gsm[(cg + 8) * GSTR + bg * 4 + 3] = hsum2(acc13) + b1;
        }
        __syncthreads();

        // ---- elementwise LSTM update (c is CTA-private) ----
        float* hnext = g_hbuf[(t + 1) & 1];
        #pragma unroll
        for (int r = 0; r < 2; ++r) {
            int e = tid + r * NTHR;       // 0..255 = 64 batch x 4 cols
            int j = e & 3;
            int b = e >> 2;
            float fg = sigmoidf_(gsm[(0 * JCOL + j) * GSTR + b]);
            float ig = sigmoidf_(gsm[(1 * JCOL + j) * GSTR + b]);
            float og = sigmoidf_(gsm[(2 * JCOL + j) * GSTR + b]);
            float cc = tanhf    (gsm[(3 * JCOL + j) * GSTR + b]);
            float cold = csm[j * BATCH + b];
            float cnew = fg * cold + ig * cc;
            csm[j * BATCH + b] = cnew;
            float h = og * tanhf(cnew);
            hnext[b * HDIM + j0 + j] = h;
            hseq[((size_t)t * BATCH + b) * HDIM + j0 + j] = h;
            if (t == T_STEPS - 1) {
                hfin[b * HDIM + j0 + j] = h;
                cfin[b * HDIM + j0 + j] = cnew;
            }
        }

        // ---- grid barrier between steps (epoch-based, wrap-safe) ----
        if (t < T_STEPS - 1) {
            __threadfence();              // publish h stores device-wide
            __syncthreads();
            if (tid == 0) {
                unsigned target = base_epoch + (unsigned)(t + 1);
                unsigned old = atomicAdd(&g_bar_count, 1u);
                if (old == NCTA - 1) {
                    atomicExch(&g_bar_count, 0u);
                    __threadfence();
                    atomicAdd(&g_bar_epoch, 1u);
                } else {
                    while ((int)(*(volatile unsigned*)&g_bar_epoch - target) < 0) { }
                }
                __threadfence();          // acquire
            }
            __syncthreads();
        }
#undef INNER_CHUNK
    }
}

extern "C" void kernel_launch(void* const* d_in, const int* in_sizes, int n_in,
                              void* d_out, int out_size)
{
    (void)in_sizes; (void)n_in; (void)out_size;
    const float* x   = (const float*)d_in[0];
    const float* Wf  = (const float*)d_in[1];
    const float* bWf = (const float*)d_in[2];
    const float* Wi  = (const float*)d_in[3];
    const float* bWi = (const float*)d_in[4];
    const float* Wo  = (const float*)d_in[5];
    const float* bWo = (const float*)d_in[6];
    const float* Wc  = (const float*)d_in[7];
    const float* bWc = (const float*)d_in[8];
    const float* Uf  = (const float*)d_in[9];
    const float* bUf = (const float*)d_in[10];
    const float* Ui  = (const float*)d_in[11];
    const float* bUi = (const float*)d_in[12];
    const float* Uo  = (const float*)d_in[13];
    const float* bUo = (const float*)d_in[14];
    const float* Uc  = (const float*)d_in[15];
    const float* bUc = (const float*)d_in[16];

    size_t smem_bytes = SMEM_FLOATS * sizeof(float);
    cudaFuncSetAttribute(lstm_persistent,
                         cudaFuncAttributeMaxDynamicSharedMemorySize,
                         (int)smem_bytes);

    lstm_persistent<<<NCTA, NTHR, smem_bytes>>>(
        x, Wf, bWf, Wi, bWi, Wo, bWo, Wc, bWc,
        Uf, bUf, Ui, bUi, Uo, bUo, Uc, bUc,
        (float*)d_out);
}

// round 2
// speedup vs baseline: 1.0308x; 1.0308x over previous
#include <cuda_runtime.h>

#define T_STEPS 512
#define BATCH   64
#define IDIM    256
#define HDIM    512
#define NCTA    128
#define NTHR    256
#define JCOL    4            // h-columns per CTA
#define GR      16           // gate rows per CTA (4 gates * JCOL)
#define CK      64           // K staging chunk
#define CKP     68           // padded chunk row stride (floats), 272B: 16B aligned, +4 banks/row
#define WXS     260          // Wx row stride (floats): 16B aligned, +4 banks/row
#define WHS     516          // Wh row stride (floats): 16B aligned, +4 banks/row
#define GSTR    66           // gate-exchange row stride

typedef unsigned long long ull;

// persistent state (static device arrays: no allocation in kernel_launch)
__device__ float g_hbuf[2][BATCH * HDIM];
__device__ unsigned int g_bar_count;
__device__ unsigned int g_bar_epoch;

__device__ __forceinline__ ull fma2(ull a, ull b, ull c) {
    ull d;
    asm("fma.rn.f32x2 %0, %1, %2, %3;" : "=l"(d) : "l"(a), "l"(b), "l"(c));
    return d;
}

__device__ __forceinline__ float hsum2(ull a) {
    return __uint_as_float((unsigned)(a & 0xffffffffu)) +
           __uint_as_float((unsigned)(a >> 32));
}

__device__ __forceinline__ float sigmoidf_(float v) {
    return __fdividef(1.0f, 1.0f + __expf(-v));
}

// shared layout (floats)
#define OFF_WX   0
#define OFF_WH   (OFF_WX + GR * WXS)            // 4160
#define OFF_ASH  (OFF_WH + GR * WHS)            // +8256
#define OFF_GSM  (OFF_ASH + 2 * BATCH * CKP)    // +8704
#define OFF_CSM  (OFF_GSM + 2 * GR * GSTR)      // +2112
#define OFF_BSM  (OFF_CSM + JCOL * BATCH)       // +256
#define OFF_EB   (OFF_BSM + GR)                 // +16
#define SMEM_FLOATS (OFF_EB + 4)

// 16-wide fma2 update for one 4-float slab of w0/w1 against 4 activation rows
#define MACBLK(kkv)                                                        \
    {                                                                      \
        ulonglong2 w0v = *(const ulonglong2*)(w0 + (kkv));                 \
        ulonglong2 w1v = *(const ulonglong2*)(w1 + (kkv));                 \
        ulonglong2 av;                                                     \
        av = *(const ulonglong2*)(a0p + (kkv));                            \
        A0  = fma2(w0v.x, av.x, A0);  A1  = fma2(w0v.y, av.y, A1);         \
        A2  = fma2(w1v.x, av.x, A2);  A3  = fma2(w1v.y, av.y, A3);         \
        av = *(const ulonglong2*)(a1p + (kkv));                            \
        A4  = fma2(w0v.x, av.x, A4);  A5  = fma2(w0v.y, av.y, A5);         \
        A6  = fma2(w1v.x, av.x, A6);  A7  = fma2(w1v.y, av.y, A7);         \
        av = *(const ulonglong2*)(a2p + (kkv));                            \
        A8  = fma2(w0v.x, av.x, A8);  A9  = fma2(w0v.y, av.y, A9);         \
        A10 = fma2(w1v.x, av.x, A10); A11 = fma2(w1v.y, av.y, A11);        \
        av = *(const ulonglong2*)(a3p + (kkv));                            \
        A12 = fma2(w0v.x, av.x, A12); A13 = fma2(w0v.y, av.y, A13);        \
        A14 = fma2(w1v.x, av.x, A14); A15 = fma2(w1v.y, av.y, A15);        \
    }

__global__ void __launch_bounds__(NTHR, 1)
lstm_persistent(const float* __restrict__ x,
                const float* __restrict__ Wf, const float* __restrict__ bWf,
                const float* __restrict__ Wi, const float* __restrict__ bWi,
                const float* __restrict__ Wo, const float* __restrict__ bWo,
                const float* __restrict__ Wc, const float* __restrict__ bWc,
                const float* __restrict__ Uf, const float* __restrict__ bUf,
                const float* __restrict__ Ui, const float* __restrict__ bUi,
                const float* __restrict__ Uo, const float* __restrict__ bUo,
                const float* __restrict__ Uc, const float* __restrict__ bUc,
                float* __restrict__ out)
{
    extern __shared__ float sm[];
    float* Wx  = sm + OFF_WX;                  // GR * WXS
    float* Wh  = sm + OFF_WH;                  // GR * WHS
    float* ash = sm + OFF_ASH;                 // 2 * BATCH * CKP (double buffer)
    float* gsm = sm + OFF_GSM;                 // 2 * GR * GSTR (two K-half partials)
    float* csm = sm + OFF_CSM;                 // JCOL * BATCH
    float* bsm = sm + OFF_BSM;                 // GR
    unsigned* ebase = (unsigned*)(sm + OFF_EB);

    const int tid = threadIdx.x;
    const int kh  = tid >> 7;                  // K-half: 0 or 1
    const int tl  = tid & 127;
    const int cg  = tl & 7;                    // gate rows cg, cg+8
    const int bg  = tl >> 3;                   // batch group of 4 (0..15)
    const int j0  = blockIdx.x * JCOL;

    // ---- prologue: weights + bias into SMEM, c state = 0 ----
    {
        const float* Wg[4]  = {Wf, Wi, Wo, Wc};
        const float* Ug[4]  = {Uf, Ui, Uo, Uc};
        const float* bWg[4] = {bWf, bWi, bWo, bWc};
        const float* bUg[4] = {bUf, bUi, bUo, bUc};

        for (int idx = tid; idx < GR * IDIM; idx += NTHR) {
            int row = idx >> 8, k = idx & (IDIM - 1);
            int gate = row >> 2, j = row & 3;
            Wx[row * WXS + k] = Wg[gate][(j0 + j) * IDIM + k];
        }
        for (int idx = tid; idx < GR * HDIM; idx += NTHR) {
            int row = idx >> 9, k = idx & (HDIM - 1);
            int gate = row >> 2, j = row & 3;
            Wh[row * WHS + k] = Ug[gate][(j0 + j) * HDIM + k];
        }
        if (tid < GR) {
            int gate = tid >> 2, j = tid & 3;
            bsm[tid] = bWg[gate][j0 + j] + bUg[gate][j0 + j];
        }
        csm[tid] = 0.0f;                       // exactly 256 entries
        if (tid == 0) *ebase = *(volatile unsigned*)&g_bar_epoch;
    }
    __syncthreads();
    const unsigned base_epoch = *ebase;

    float* hseq = out;
    float* hfin = out + (size_t)T_STEPS * BATCH * HDIM;
    float* cfin = hfin + BATCH * HDIM;

    // per-thread fixed pointers (K-half offset folded in)
    const float* wx0 = Wx + cg * WXS + kh * 32;
    const float* wx1 = Wx + (cg + 8) * WXS + kh * 32;
    const float* wh0 = Wh + cg * WHS + kh * 32;
    const float* wh1 = Wh + (cg + 8) * WHS + kh * 32;

    // stage chunk0 of t=0 (x data) into buffer 0
    {
        const float* src = x;                  // t=0, chunk 0
        #pragma unroll
        for (int r = 0; r < 4; ++r) {
            int idx = tid + r * NTHR;
            int b = idx >> 4, q = idx & 15;
            float4 v = __ldg(reinterpret_cast<const float4*>(src + b * IDIM + q * 4));
            *reinterpret_cast<float4*>(ash + b * CKP + q * 4) = v;
        }
    }

    for (int t = 0; t < T_STEPS; ++t) {
        const int nc = (t == 0) ? 4 : 12;
        const float* xt = x + (size_t)t * BATCH * IDIM;
        const float* hprev = g_hbuf[t & 1];

        ull A0=0,A1=0,A2=0,A3=0,A4=0,A5=0,A6=0,A7=0;
        ull A8=0,A9=0,A10=0,A11=0,A12=0,A13=0,A14=0,A15=0;

        for (int c = 0; c < nc; ++c) {
            __syncthreads();                   // stage(c) visible; buf[(c+1)&1] free

            // prefetch chunk c+1 into the other buffer
            if (c + 1 < nc) {
                const int cn = c + 1;
                float* dst = ash + ((cn & 1) ? BATCH * CKP : 0);
                if (cn < 4) {
                    const float* src = xt + cn * CK;
                    #pragma unroll
                    for (int r = 0; r < 4; ++r) {
                        int idx = tid + r * NTHR;
                        int b = idx >> 4, q = idx & 15;
                        float4 v = __ldg(reinterpret_cast<const float4*>(src + b * IDIM + q * 4));
                        *reinterpret_cast<float4*>(dst + b * CKP + q * 4) = v;
                    }
                } else {
                    const float* src = hprev + (cn - 4) * CK;
                    #pragma unroll
                    for (int r = 0; r < 4; ++r) {
                        int idx = tid + r * NTHR;
                        int b = idx >> 4, q = idx & 15;
                        float4 v = __ldcg(reinterpret_cast<const float4*>(src + b * HDIM + q * 4));
                        *reinterpret_cast<float4*>(dst + b * CKP + q * 4) = v;
                    }
                }
            }

            // compute chunk c from buf[c&1]
            {
                const float* abase = ash + ((c & 1) ? BATCH * CKP : 0) + kh * 32;
                const float* a0p = abase + (bg * 4 + 0) * CKP;
                const float* a1p = abase + (bg * 4 + 1) * CKP;
                const float* a2p = abase + (bg * 4 + 2) * CKP;
                const float* a3p = abase + (bg * 4 + 3) * CKP;
                const float* w0  = (c < 4) ? (wx0 + c * CK) : (wh0 + (c - 4) * CK);
                const float* w1  = (c < 4) ? (wx1 + c * CK) : (wh1 + (c - 4) * CK);
                #pragma unroll
                for (int kk = 0; kk < 32; kk += 4) MACBLK(kk)
            }
        }

        // ---- write K-half partial gate sums ----
        {
            float* g0 = gsm + kh * GR * GSTR + cg * GSTR + bg * 4;
            float* g1 = gsm + kh * GR * GSTR + (cg + 8) * GSTR + bg * 4;
            g0[0] = hsum2(A0)  + hsum2(A1);
            g1[0] = hsum2(A2)  + hsum2(A3);
            g0[1] = hsum2(A4)  + hsum2(A5);
            g1[1] = hsum2(A6)  + hsum2(A7);
            g0[2] = hsum2(A8)  + hsum2(A9);
            g1[2] = hsum2(A10) + hsum2(A11);
            g0[3] = hsum2(A12) + hsum2(A13);
            g1[3] = hsum2(A14) + hsum2(A15);
        }
        __syncthreads();

        // ---- elementwise LSTM update (one element per thread) ----
        float* hnext = g_hbuf[(t + 1) & 1];
        {
            int j = tid & 3;
            int b = tid >> 2;
            float gf = gsm[(0*JCOL+j)*GSTR + b] + gsm[GR*GSTR + (0*JCOL+j)*GSTR + b] + bsm[0*JCOL+j];
            float gi = gsm[(1*JCOL+j)*GSTR + b] + gsm[GR*GSTR + (1*JCOL+j)*GSTR + b] + bsm[1*JCOL+j];
            float go = gsm[(2*JCOL+j)*GSTR + b] + gsm[GR*GSTR + (2*JCOL+j)*GSTR + b] + bsm[2*JCOL+j];
            float gc = gsm[(3*JCOL+j)*GSTR + b] + gsm[GR*GSTR + (3*JCOL+j)*GSTR + b] + bsm[3*JCOL+j];
            float fg = sigmoidf_(gf);
            float ig = sigmoidf_(gi);
            float og = sigmoidf_(go);
            float cc = tanhf(gc);
            float cold = csm[tid];
            float cnew = fg * cold + ig * cc;
            csm[tid] = cnew;
            float h = og * tanhf(cnew);
            hnext[b * HDIM + j0 + j] = h;
            hseq[((size_t)t * BATCH + b) * HDIM + j0 + j] = h;
            if (t == T_STEPS - 1) {
                hfin[b * HDIM + j0 + j] = h;
                cfin[b * HDIM + j0 + j] = cnew;
            }
        }

        // ---- prefetch next step's x chunk0 (independent of h), then grid barrier ----
        if (t < T_STEPS - 1) {
            const float* src = x + (size_t)(t + 1) * BATCH * IDIM;
            #pragma unroll
            for (int r = 0; r < 4; ++r) {
                int idx = tid + r * NTHR;
                int b = idx >> 4, q = idx & 15;
                float4 v = __ldg(reinterpret_cast<const float4*>(src + b * IDIM + q * 4));
                *reinterpret_cast<float4*>(ash + b * CKP + q * 4) = v;
            }

            __threadfence();               // publish h stores device-wide
            __syncthreads();
            if (tid == 0) {
                unsigned target = base_epoch + (unsigned)(t + 1);
                unsigned old = atomicAdd(&g_bar_count, 1u);
                if (old == NCTA - 1) {
                    atomicExch(&g_bar_count, 0u);
                    __threadfence();
                    atomicAdd(&g_bar_epoch, 1u);
                } else {
                    while ((int)(*(volatile unsigned*)&g_bar_epoch - target) < 0) { }
                }
                __threadfence();           // acquire
            }
            __syncthreads();
        }
    }
}

extern "C" void kernel_launch(void* const* d_in, const int* in_sizes, int n_in,
                              void* d_out, int out_size)
{
    (void)in_sizes; (void)n_in; (void)out_size;
    const float* x   = (const float*)d_in[0];
    const float* Wf  = (const float*)d_in[1];
    const float* bWf = (const float*)d_in[2];
    const float* Wi  = (const float*)d_in[3];
    const float* bWi = (const float*)d_in[4];
    const float* Wo  = (const float*)d_in[5];
    const float* bWo = (const float*)d_in[6];
    const float* Wc  = (const float*)d_in[7];
    const float* bWc = (const float*)d_in[8];
    const float* Uf  = (const float*)d_in[9];
    const float* bUf = (const float*)d_in[10];
    const float* Ui  = (const float*)d_in[11];
    const float* bUi = (const float*)d_in[12];
    const float* Uo  = (const float*)d_in[13];
    const float* bUo = (const float*)d_in[14];
    const float* Uc  = (const float*)d_in[15];
    const float* bUc = (const float*)d_in[16];

    size_t smem_bytes = SMEM_FLOATS * sizeof(float);
    cudaFuncSetAttribute(lstm_persistent,
                         cudaFuncAttributeMaxDynamicSharedMemorySize,
                         (int)smem_bytes);

    lstm_persistent<<<NCTA, NTHR, smem_bytes>>>(
        x, Wf, bWf, Wi, bWi, Wo, bWo, Wc, bWc,
        Uf, bUf, Ui, bUi, Uo, bUo, Uc, bUc,
        (float*)d_out);
}

// round 3
// speedup vs baseline: 1.3472x; 1.3069x over previous
#include <cuda_runtime.h>

#define T_STEPS 512
#define BATCH   64
#define IDIM    256
#define HDIM    512
#define NCTA    128
#define NTHR    256
#define JCOL    4
#define GR      16            // gate rows per CTA
#define GSTR    68            // gate-exchange row stride (16B-aligned, +4 banks)

typedef unsigned long long ull;

// ---- persistent device scratch (static: no runtime allocation) ----
__device__ float g_xw[(size_t)T_STEPS * NCTA * GR * BATCH];   // 268MB: [t][cta][row][b], bias folded in
__device__ float g_hbuf[2][BATCH * HDIM];
__device__ unsigned int g_bar_count;
__device__ unsigned int g_bar_epoch;

__device__ __forceinline__ ull fma2(ull a, ull b, ull c) {
    ull d;
    asm("fma.rn.f32x2 %0, %1, %2, %3;" : "=l"(d) : "l"(a), "l"(b), "l"(c));
    return d;
}
__device__ __forceinline__ float hsum2(ull a) {
    return __uint_as_float((unsigned)(a & 0xffffffffu)) +
           __uint_as_float((unsigned)(a >> 32));
}
__device__ __forceinline__ float sigmoidf_(float v) {
    return __fdividef(1.0f, 1.0f + __expf(-v));
}

// 16-wide fma2 update: one 4-float k-slab of w0/w1 against 4 activation rows
#define MACBLK(kkv)                                                        \
    {                                                                      \
        ulonglong2 w0v = *(const ulonglong2*)(w0 + (kkv));                 \
        ulonglong2 w1v = *(const ulonglong2*)(w1 + (kkv));                 \
        ulonglong2 av;                                                     \
        av = *(const ulonglong2*)(a0p + (kkv));                            \
        A0  = fma2(w0v.x, av.x, A0);  A1  = fma2(w0v.y, av.y, A1);         \
        A2  = fma2(w1v.x, av.x, A2);  A3  = fma2(w1v.y, av.y, A3);         \
        av = *(const ulonglong2*)(a1p + (kkv));                            \
        A4  = fma2(w0v.x, av.x, A4);  A5  = fma2(w0v.y, av.y, A5);         \
        A6  = fma2(w1v.x, av.x, A6);  A7  = fma2(w1v.y, av.y, A7);         \
        av = *(const ulonglong2*)(a2p + (kkv));                            \
        A8  = fma2(w0v.x, av.x, A8);  A9  = fma2(w0v.y, av.y, A9);         \
        A10 = fma2(w1v.x, av.x, A10); A11 = fma2(w1v.y, av.y, A11);        \
        av = *(const ulonglong2*)(a3p + (kkv));                            \
        A12 = fma2(w0v.x, av.x, A12); A13 = fma2(w0v.y, av.y, A13);        \
        A14 = fma2(w1v.x, av.x, A14); A15 = fma2(w1v.y, av.y, A15);        \
    }

// ============================================================================
// Phase 1: xw[t] = x_t @ Wall^T + (bW + bU), fully parallel.
// grid (128 j-groups, 64 t-groups of 8), 256 threads, 2 CTAs/SM.
// ============================================================================
#define P1_WXS  260           // W row stride (K=256 + pad)
#define P1_CKP  132           // act row stride (K-chunk 128 + pad)
#define P1_OFF_WX   0
#define P1_OFF_ASH  (P1_OFF_WX + GR * P1_WXS)          // 4160
#define P1_OFF_GSM  (P1_OFF_ASH + 2 * BATCH * P1_CKP)  // +16896
#define P1_OFF_BS   (P1_OFF_GSM + 2 * GR * GSTR)       // +2176
#define P1_FLOATS   (P1_OFF_BS + GR)

__global__ void __launch_bounds__(NTHR, 2)
lstm_xw_kernel(const float* __restrict__ x,
               const float* __restrict__ Wf, const float* __restrict__ bWf,
               const float* __restrict__ Wi, const float* __restrict__ bWi,
               const float* __restrict__ Wo, const float* __restrict__ bWo,
               const float* __restrict__ Wc, const float* __restrict__ bWc,
               const float* __restrict__ bUf, const float* __restrict__ bUi,
               const float* __restrict__ bUo, const float* __restrict__ bUc)
{
    extern __shared__ float sm[];
    float* Wx  = sm + P1_OFF_WX;
    float* ash = sm + P1_OFF_ASH;
    float* gsm = sm + P1_OFF_GSM;
    float* bsm = sm + P1_OFF_BS;

    const int tid = threadIdx.x;
    const int kh  = tid >> 7;
    const int tl  = tid & 127;
    const int cg  = tl & 7;
    const int bg  = tl >> 3;
    const int jg  = blockIdx.x;
    const int j0  = jg * JCOL;
    const int t0  = blockIdx.y * 8;

    {
        const float* Wg[4]  = {Wf, Wi, Wo, Wc};
        const float* bWg[4] = {bWf, bWi, bWo, bWc};
        const float* bUg[4] = {bUf, bUi, bUo, bUc};
        for (int idx = tid; idx < GR * IDIM; idx += NTHR) {
            int row = idx >> 8, k = idx & (IDIM - 1);
            int gate = row >> 2, j = row & 3;
            Wx[row * P1_WXS + k] = Wg[gate][(j0 + j) * IDIM + k];
        }
        if (tid < GR) {
            int gate = tid >> 2, j = tid & 3;
            bsm[tid] = bWg[gate][j0 + j] + bUg[gate][j0 + j];
        }
    }
    __syncthreads();

    const float* w0b = Wx + cg * P1_WXS + kh * 64;
    const float* w1b = Wx + (cg + 8) * P1_WXS + kh * 64;

    for (int tt = 0; tt < 8; ++tt) {
        const int t = t0 + tt;
        const float* xt = x + (size_t)t * BATCH * IDIM;

        // stage chunk0 (k 0:128)
        #pragma unroll
        for (int r = 0; r < 8; ++r) {
            int idx = tid + r * NTHR;
            int b = idx >> 5, q = idx & 31;
            float4 v = __ldg(reinterpret_cast<const float4*>(xt + b * IDIM + q * 4));
            *reinterpret_cast<float4*>(ash + b * P1_CKP + q * 4) = v;
        }
        __syncthreads();

        ull A0=0,A1=0,A2=0,A3=0,A4=0,A5=0,A6=0,A7=0;
        ull A8=0,A9=0,A10=0,A11=0,A12=0,A13=0,A14=0,A15=0;

        // prefetch chunk1 (k 128:256)
        #pragma unroll
        for (int r = 0; r < 8; ++r) {
            int idx = tid + r * NTHR;
            int b = idx >> 5, q = idx & 31;
            float4 v = __ldg(reinterpret_cast<const float4*>(xt + b * IDIM + 128 + q * 4));
            *reinterpret_cast<float4*>(ash + BATCH * P1_CKP + b * P1_CKP + q * 4) = v;
        }
        // compute chunk0
        {
            const float* abase = ash + kh * 64;
            const float* a0p = abase + (bg * 4 + 0) * P1_CKP;
            const float* a1p = abase + (bg * 4 + 1) * P1_CKP;
            const float* a2p = abase + (bg * 4 + 2) * P1_CKP;
            const float* a3p = abase + (bg * 4 + 3) * P1_CKP;
            const float* w0 = w0b;
            const float* w1 = w1b;
            #pragma unroll
            for (int kk = 0; kk < 64; kk += 4) MACBLK(kk)
        }
        __syncthreads();
        // compute chunk1
        {
            const float* abase = ash + BATCH * P1_CKP + kh * 64;
            const float* a0p = abase + (bg * 4 + 0) * P1_CKP;
            const float* a1p = abase + (bg * 4 + 1) * P1_CKP;
            const float* a2p = abase + (bg * 4 + 2) * P1_CKP;
            const float* a3p = abase + (bg * 4 + 3) * P1_CKP;
            const float* w0 = w0b + 128;
            const float* w1 = w1b + 128;
            #pragma unroll
            for (int kk = 0; kk < 64; kk += 4) MACBLK(kk)
        }
        // write K-half partials
        {
            float* g0 = gsm + kh * GR * GSTR + cg * GSTR + bg * 4;
            float* g1 = gsm + kh * GR * GSTR + (cg + 8) * GSTR + bg * 4;
            g0[0] = hsum2(A0)  + hsum2(A1);
            g1[0] = hsum2(A2)  + hsum2(A3);
            g0[1] = hsum2(A4)  + hsum2(A5);
            g1[1] = hsum2(A6)  + hsum2(A7);
            g0[2] = hsum2(A8)  + hsum2(A9);
            g1[2] = hsum2(A10) + hsum2(A11);
            g0[3] = hsum2(A12) + hsum2(A13);
            g1[3] = hsum2(A14) + hsum2(A15);
        }
        __syncthreads();
        // combine + store: 4 outputs per thread (float4 over b)
        {
            int row = tid >> 4;
            int b4  = (tid & 15) * 4;
            float4 p0 = *reinterpret_cast<float4*>(gsm + row * GSTR + b4);
            float4 p1 = *reinterpret_cast<float4*>(gsm + GR * GSTR + row * GSTR + b4);
            float bb = bsm[row];
            float4 o;
            o.x = p0.x + p1.x + bb;
            o.y = p0.y + p1.y + bb;
            o.z = p0.z + p1.z + bb;
            o.w = p0.w + p1.w + bb;
            *reinterpret_cast<float4*>(g_xw + (((size_t)t * NCTA + jg) * GR + row) * BATCH + b4) = o;
        }
        __syncthreads();   // gsm/ash safe for next tt
    }
}

// ============================================================================
// Phase 2: persistent recurrence. h @ U^T only; xw read from g_xw.
// ============================================================================
#define P2_WHS  516           // U row stride (K=512 + pad)
#define P2_CKP  260           // act row stride (K-chunk 256 + pad)
#define P2_OFF_WH   0
#define P2_OFF_ASH  (P2_OFF_WH + GR * P2_WHS)          // 8256
#define P2_OFF_GSM  (P2_OFF_ASH + 2 * BATCH * P2_CKP)  // +33280
#define P2_OFF_XW   (P2_OFF_GSM + 2 * GR * GSTR)       // +2176
#define P2_OFF_CSM  (P2_OFF_XW + GR * GSTR)            // +1088
#define P2_OFF_EB   (P2_OFF_CSM + NTHR)                // +256
#define P2_FLOATS   (P2_OFF_EB + 4)

__global__ void __launch_bounds__(NTHR, 1)
lstm_recur_kernel(const float* __restrict__ Uf, const float* __restrict__ Ui,
                  const float* __restrict__ Uo, const float* __restrict__ Uc,
                  float* __restrict__ out)
{
    extern __shared__ float sm[];
    float* Wh   = sm + P2_OFF_WH;
    float* ash  = sm + P2_OFF_ASH;
    float* gsm  = sm + P2_OFF_GSM;
    float* xwsm = sm + P2_OFF_XW;
    float* csm  = sm + P2_OFF_CSM;
    unsigned* ebase = (unsigned*)(sm + P2_OFF_EB);

    const int tid = threadIdx.x;
    const int kh  = tid >> 7;
    const int tl  = tid & 127;
    const int cg  = tl & 7;
    const int bg  = tl >> 3;
    const int j0  = blockIdx.x * JCOL;

    {
        const float* Ug[4] = {Uf, Ui, Uo, Uc};
        for (int idx = tid; idx < GR * HDIM; idx += NTHR) {
            int row = idx >> 9, k = idx & (HDIM - 1);
            int gate = row >> 2, j = row & 3;
            Wh[row * P2_WHS + k] = Ug[gate][(j0 + j) * HDIM + k];
        }
        csm[tid] = 0.0f;
        if (tid == 0) *ebase = *(volatile unsigned*)&g_bar_epoch;
    }
    __syncthreads();
    const unsigned base_epoch = *ebase;

    float* hseq = out;
    float* hfin = out + (size_t)T_STEPS * BATCH * HDIM;
    float* cfin = hfin + BATCH * HDIM;

    const float* w0b = Wh + cg * P2_WHS + kh * 128;
    const float* w1b = Wh + (cg + 8) * P2_WHS + kh * 128;
    const float* xwblk0 = g_xw + (size_t)blockIdx.x * GR * BATCH;

    for (int t = 0; t < T_STEPS; ++t) {
        // stage this step's xw block (4KB, contiguous) — one float4 per thread
        {
            const float* src = xwblk0 + (size_t)t * NCTA * GR * BATCH;
            int row = tid >> 4;
            int b4  = (tid & 15) * 4;
            float4 v = __ldg(reinterpret_cast<const float4*>(src + row * BATCH + b4));
            *reinterpret_cast<float4*>(xwsm + row * GSTR + b4) = v;
        }

        if (t > 0) {
            const float* hprev = g_hbuf[t & 1];

            // stage h chunk0 (k 0:256): 16 float4 per thread
            #pragma unroll
            for (int r = 0; r < 16; ++r) {
                int idx = tid + r * NTHR;
                int b = idx >> 6, q = idx & 63;
                float4 v = __ldcg(reinterpret_cast<const float4*>(hprev + b * HDIM + q * 4));
                *reinterpret_cast<float4*>(ash + b * P2_CKP + q * 4) = v;
            }
            __syncthreads();

            ull A0=0,A1=0,A2=0,A3=0,A4=0,A5=0,A6=0,A7=0;
            ull A8=0,A9=0,A10=0,A11=0,A12=0,A13=0,A14=0,A15=0;

            // prefetch chunk1 (k 256:512)
            #pragma unroll
            for (int r = 0; r < 16; ++r) {
                int idx = tid + r * NTHR;
                int b = idx >> 6, q = idx & 63;
                float4 v = __ldcg(reinterpret_cast<const float4*>(hprev + b * HDIM + 256 + q * 4));
                *reinterpret_cast<float4*>(ash + BATCH * P2_CKP + b * P2_CKP + q * 4) = v;
            }
            // compute chunk0
            {
                const float* abase = ash + kh * 128;
                const float* a0p = abase + (bg * 4 + 0) * P2_CKP;
                const float* a1p = abase + (bg * 4 + 1) * P2_CKP;
                const float* a2p = abase + (bg * 4 + 2) * P2_CKP;
                const float* a3p = abase + (bg * 4 + 3) * P2_CKP;
                const float* w0 = w0b;
                const float* w1 = w1b;
                #pragma unroll 16
                for (int kk = 0; kk < 128; kk += 4) MACBLK(kk)
            }
            __syncthreads();
            // compute chunk1
            {
                const float* abase = ash + BATCH * P2_CKP + kh * 128;
                const float* a0p = abase + (bg * 4 + 0) * P2_CKP;
                const float* a1p = abase + (bg * 4 + 1) * P2_CKP;
                const float* a2p = abase + (bg * 4 + 2) * P2_CKP;
                const float* a3p = abase + (bg * 4 + 3) * P2_CKP;
                const float* w0 = w0b + 256;
                const float* w1 = w1b + 256;
                #pragma unroll 16
                for (int kk = 0; kk < 128; kk += 4) MACBLK(kk)
            }
            // write K-half partials
            {
                float* g0 = gsm + kh * GR * GSTR + cg * GSTR + bg * 4;
                float* g1 = gsm + kh * GR * GSTR + (cg + 8) * GSTR + bg * 4;
                g0[0] = hsum2(A0)  + hsum2(A1);
                g1[0] = hsum2(A2)  + hsum2(A3);
                g0[1] = hsum2(A4)  + hsum2(A5);
                g1[1] = hsum2(A6)  + hsum2(A7);
                g0[2] = hsum2(A8)  + hsum2(A9);
                g1[2] = hsum2(A10) + hsum2(A11);
                g0[3] = hsum2(A12) + hsum2(A13);
                g1[3] = hsum2(A14) + hsum2(A15);
            }
        }
        __syncthreads();

        // elementwise LSTM update (one (j,b) element per thread)
        float* hnext = g_hbuf[(t + 1) & 1];
        {
            int j = tid & 3;
            int b = tid >> 2;
            float gf, gi, go, gc;
            if (t > 0) {
                gf = gsm[(0*JCOL+j)*GSTR + b] + gsm[GR*GSTR + (0*JCOL+j)*GSTR + b] + xwsm[(0*JCOL+j)*GSTR + b];
                gi = gsm[(1*JCOL+j)*GSTR + b] + gsm[GR*GSTR + (1*JCOL+j)*GSTR + b] + xwsm[(1*JCOL+j)*GSTR + b];
                go = gsm[(2*JCOL+j)*GSTR + b] + gsm[GR*GSTR + (2*JCOL+j)*GSTR + b] + xwsm[(2*JCOL+j)*GSTR + b];
                gc = gsm[(3*JCOL+j)*GSTR + b] + gsm[GR*GSTR + (3*JCOL+j)*GSTR + b] + xwsm[(3*JCOL+j)*GSTR + b];
            } else {
                gf = xwsm[(0*JCOL+j)*GSTR + b];
                gi = xwsm[(1*JCOL+j)*GSTR + b];
                go = xwsm[(2*JCOL+j)*GSTR + b];
                gc = xwsm[(3*JCOL+j)*GSTR + b];
            }
            float fg = sigmoidf_(gf);
            float ig = sigmoidf_(gi);
            float og = sigmoidf_(go);
            float cc = tanhf(gc);
            float cold = csm[tid];
            float cnew = fg * cold + ig * cc;
            csm[tid] = cnew;
            float h = og * tanhf(cnew);
            hnext[b * HDIM + j0 + j] = h;
            hseq[((size_t)t * BATCH + b) * HDIM + j0 + j] = h;
            if (t == T_STEPS - 1) {
                hfin[b * HDIM + j0 + j] = h;
                cfin[b * HDIM + j0 + j] = cnew;
            }
        }

        // grid barrier between steps
        if (t < T_STEPS - 1) {
            __threadfence();
            __syncthreads();
            if (tid == 0) {
                unsigned target = base_epoch + (unsigned)(t + 1);
                unsigned old = atomicAdd(&g_bar_count, 1u);
                if (old == NCTA - 1) {
                    atomicExch(&g_bar_count, 0u);
                    __threadfence();
                    atomicAdd(&g_bar_epoch, 1u);
                } else {
                    while ((int)(*(volatile unsigned*)&g_bar_epoch - target) < 0) { }
                }
                __threadfence();
            }
            __syncthreads();
        }
    }
}

extern "C" void kernel_launch(void* const* d_in, const int* in_sizes, int n_in,
                              void* d_out, int out_size)
{
    (void)in_sizes; (void)n_in; (void)out_size;
    const float* x   = (const float*)d_in[0];
    const float* Wf  = (const float*)d_in[1];
    const float* bWf = (const float*)d_in[2];
    const float* Wi  = (const float*)d_in[3];
    const float* bWi = (const float*)d_in[4];
    const float* Wo  = (const float*)d_in[5];
    const float* bWo = (const float*)d_in[6];
    const float* Wc  = (const float*)d_in[7];
    const float* bWc = (const float*)d_in[8];
    const float* Uf  = (const float*)d_in[9];
    const float* bUf = (const float*)d_in[10];
    const float* Ui  = (const float*)d_in[11];
    const float* bUi = (const float*)d_in[12];
    const float* Uo  = (const float*)d_in[13];
    const float* bUo = (const float*)d_in[14];
    const float* Uc  = (const float*)d_in[15];
    const float* bUc = (const float*)d_in[16];

    size_t p1_smem = P1_FLOATS * sizeof(float);
    size_t p2_smem = P2_FLOATS * sizeof(float);
    cudaFuncSetAttribute(lstm_xw_kernel,
                         cudaFuncAttributeMaxDynamicSharedMemorySize, (int)p1_smem);
    cudaFuncSetAttribute(lstm_recur_kernel,
                         cudaFuncAttributeMaxDynamicSharedMemorySize, (int)p2_smem);

    dim3 g1(NCTA, T_STEPS / 8);
    lstm_xw_kernel<<<g1, NTHR, p1_smem>>>(
        x, Wf, bWf, Wi, bWi, Wo, bWo, Wc, bWc, bUf, bUi, bUo, bUc);

    lstm_recur_kernel<<<NCTA, NTHR, p2_smem>>>(Uf, Ui, Uo, Uc, (float*)d_out);
}